// round 16
// baseline (speedup 1.0000x reference)
#include <cuda_runtime.h>
#include <math.h>

// ---------------- problem constants ----------------
#define B_        4
#define L_        2048
#define DM        2048      // d_model = H*P
#define H_        32
#define P_        64
#define N_        32
#define KCONV     4
#define CONV_DIM  2112      // DM + 2*N
#define PROJ_     4192      // DM + CONV_DIM + H
#define ROWS      (B_*L_)   // 8192

// ---------------- scratch (device globals; no allocations allowed) ----------------
__device__ float g_proj[(size_t)ROWS * PROJ_];     // in_proj output
__device__ float g_conv[(size_t)ROWS * CONV_DIM];  // conv+silu output
__device__ float g_dt  [ROWS * H_];
__device__ float g_dA  [ROWS * H_];
__device__ float g_y   [(size_t)ROWS * DM];        // scan output (+ D*x)
__device__ float g_yn  [(size_t)ROWS * DM];        // gated rmsnorm output

// ---------------------------------------------------------------------------
// fp32 tiled GEMM: C[M,N] = A[M,K] @ B[K,N] (+ bias[N] if bias != nullptr)
// BM=BN=128, BK=16, 256 threads, 8x8 per thread.
// Requires M%128==0 and K%16==0 (true for both GEMMs). N guarded (4192 case).
// ---------------------------------------------------------------------------
__global__ __launch_bounds__(256) void gemm128(
    const float* __restrict__ A, const float* __restrict__ Bm,
    const float* __restrict__ bias, float* __restrict__ C,
    int M, int N, int K)
{
    __shared__ float As[16][128];   // [k][m]
    __shared__ float Bs[16][128];   // [k][n]

    const int tid = threadIdx.x;
    const int tx  = tid & 15;       // n dir
    const int ty  = tid >> 4;       // m dir
    const int row0 = blockIdx.y * 128;
    const int col0 = blockIdx.x * 128;

    float acc[8][8];
#pragma unroll
    for (int i = 0; i < 8; i++)
#pragma unroll
        for (int j = 0; j < 8; j++) acc[i][j] = 0.f;

    for (int k0 = 0; k0 < K; k0 += 16) {
        // load A tile (128x16), store transposed [k][m]
#pragma unroll
        for (int r = 0; r < 2; r++) {
            int u    = tid + r * 256;        // 512 float4 units
            int arow = u >> 2;               // 0..127
            int ac   = (u & 3) * 4;          // 0,4,8,12
            float4 v = *(const float4*)(A + (size_t)(row0 + arow) * K + k0 + ac);
            As[ac + 0][arow] = v.x;
            As[ac + 1][arow] = v.y;
            As[ac + 2][arow] = v.z;
            As[ac + 3][arow] = v.w;
        }
        // load B tile (16x128) [k][n], guard ragged N
#pragma unroll
        for (int r = 0; r < 2; r++) {
            int u    = tid + r * 256;
            int brow = u >> 5;               // 0..15
            int bc   = (u & 31) * 4;         // 0..124
            int gcol = col0 + bc;
            float4 v = make_float4(0.f, 0.f, 0.f, 0.f);
            if (gcol < N)                    // N%4==0 and bc%4==0 -> whole float4 valid
                v = *(const float4*)(Bm + (size_t)(k0 + brow) * N + gcol);
            *(float4*)(&Bs[brow][bc]) = v;
        }
        __syncthreads();

#pragma unroll
        for (int k = 0; k < 16; k++) {
            float a[8], b[8];
#pragma unroll
            for (int i = 0; i < 8; i++) a[i] = As[k][ty * 8 + i];
#pragma unroll
            for (int j = 0; j < 8; j++) b[j] = Bs[k][tx * 8 + j];
#pragma unroll
            for (int i = 0; i < 8; i++)
#pragma unroll
                for (int j = 0; j < 8; j++)
                    acc[i][j] = fmaf(a[i], b[j], acc[i][j]);
        }
        __syncthreads();
    }

    // epilogue
#pragma unroll
    for (int i = 0; i < 8; i++) {
        int r = row0 + ty * 8 + i;
#pragma unroll
        for (int j = 0; j < 8; j += 4) {
            int c = col0 + tx * 8 + j;
            if (c < N) {
                float4 v;
                v.x = acc[i][j + 0];
                v.y = acc[i][j + 1];
                v.z = acc[i][j + 2];
                v.w = acc[i][j + 3];
                if (bias) {
                    v.x += bias[c + 0];
                    v.y += bias[c + 1];
                    v.z += bias[c + 2];
                    v.w += bias[c + 3];
                }
                *(float4*)(C + (size_t)r * N + c) = v;
            }
        }
    }
}

// ---------------------------------------------------------------------------
// causal depthwise conv1d (K=4, left pad 3) over hBC slice of proj, then SiLU
// ---------------------------------------------------------------------------
__global__ __launch_bounds__(256) void conv_silu_kernel(
    const float* __restrict__ proj, const float* __restrict__ conv_w,
    const float* __restrict__ conv_b, float* __restrict__ out)
{
    int idx = blockIdx.x * 256 + threadIdx.x;
    if (idx >= ROWS * CONV_DIM) return;
    int c  = idx % CONV_DIM;
    int bl = idx / CONV_DIM;
    int l  = bl % L_;
    int b  = bl / L_;

    float acc = conv_b[c];
#pragma unroll
    for (int k = 0; k < KCONV; k++) {
        int t = l - (KCONV - 1) + k;
        if (t >= 0)
            acc = fmaf(proj[(size_t)(b * L_ + t) * PROJ_ + DM + c],
                       conv_w[c * KCONV + k], acc);
    }
    out[idx] = acc / (1.f + expf(-acc));   // SiLU
}

// ---------------------------------------------------------------------------
// dt = softplus(dt_raw + dt_bias); dA = exp(dt * (-exp(A_log)))
// ---------------------------------------------------------------------------
__global__ __launch_bounds__(256) void dt_kernel(
    const float* __restrict__ proj, const float* __restrict__ dt_bias,
    const float* __restrict__ A_log, float* __restrict__ dt,
    float* __restrict__ dA)
{
    int idx = blockIdx.x * 256 + threadIdx.x;
    if (idx >= ROWS * H_) return;
    int row = idx >> 5;
    int h   = idx & 31;
    float z = proj[(size_t)row * PROJ_ + DM + CONV_DIM + h] + dt_bias[h];
    float d = (z > 20.f) ? z : log1pf(expf(z));
    float a = -expf(A_log[h]);
    dt[idx] = d;
    dA[idx] = expf(d * a);
}

// ---------------------------------------------------------------------------
// selective scan: one CTA per (b,h). 256 threads; thread t handles
// p = t>>2, n in [ (t&3)*8, (t&3)*8+8 ). State in registers. Chunked staging.
// y[b,t,h*64+p] = sum_n h_state[p,n]*C[n] + D[h]*x[p]
// ---------------------------------------------------------------------------
__global__ __launch_bounds__(256) void scan_kernel(
    const float* __restrict__ conv, const float* __restrict__ dt,
    const float* __restrict__ dA, const float* __restrict__ Dp,
    float* __restrict__ y)
{
    const int bh = blockIdx.x;
    const int b  = bh >> 5;
    const int h  = bh & 31;
    const int tid = threadIdx.x;
    const int p = tid >> 2;
    const int j = tid & 3;

    __shared__ float xs[16][64];
    __shared__ float Bsh[16][32];
    __shared__ float Csh[16][32];
    __shared__ float ysh[16][64];
    __shared__ float dts[16];
    __shared__ float dAs[16];

    float s[8];
#pragma unroll
    for (int q = 0; q < 8; q++) s[q] = 0.f;
    const float Dh = Dp[h];

    for (int t0 = 0; t0 < L_; t0 += 16) {
        // stage 16 timesteps
        for (int idx = tid; idx < 16 * 128; idx += 256) {
            int tt = idx >> 7;
            int cc = idx & 127;
            size_t base = (size_t)(b * L_ + t0 + tt) * CONV_DIM;
            if (cc < 64)      xs[tt][cc]       = conv[base + h * 64 + cc];
            else if (cc < 96) Bsh[tt][cc - 64] = conv[base + DM + (cc - 64)];
            else              Csh[tt][cc - 96] = conv[base + DM + N_ + (cc - 96)];
        }
        if (tid < 16)      dts[tid]      = dt[(size_t)(b * L_ + t0 + tid) * H_ + h];
        else if (tid < 32) dAs[tid - 16] = dA[(size_t)(b * L_ + t0 + tid - 16) * H_ + h];
        __syncthreads();

#pragma unroll 1
        for (int tt = 0; tt < 16; tt++) {
            float dtv = dts[tt];
            float dav = dAs[tt];
            float xp  = xs[tt][p];
            float dtx = dtv * xp;
            float acc = 0.f;
#pragma unroll
            for (int q = 0; q < 8; q++) {
                float Bn = Bsh[tt][j * 8 + q];
                s[q] = fmaf(dav, s[q], dtx * Bn);
                acc  = fmaf(s[q], Csh[tt][j * 8 + q], acc);
            }
            acc += __shfl_xor_sync(0xffffffffu, acc, 1);
            acc += __shfl_xor_sync(0xffffffffu, acc, 2);
            if (j == 0) ysh[tt][p] = fmaf(Dh, xp, acc);
        }
        __syncthreads();

        for (int idx = tid; idx < 16 * 64; idx += 256) {
            int tt = idx >> 6;
            int pp = idx & 63;
            y[(size_t)(b * L_ + t0 + tt) * DM + h * 64 + pp] = ysh[tt][pp];
        }
        __syncthreads();
    }
}

// ---------------------------------------------------------------------------
// gated RMSNorm: g = y * silu(gate); out = g * rsqrt(mean(g^2)+eps) * norm_w
// one CTA per row, 256 threads x 8 cols each
// ---------------------------------------------------------------------------
__global__ __launch_bounds__(256) void rmsnorm_kernel(
    const float* __restrict__ y, const float* __restrict__ proj,
    const float* __restrict__ nw, float* __restrict__ out)
{
    const int row = blockIdx.x;
    const float* yr = y    + (size_t)row * DM;
    const float* gr = proj + (size_t)row * PROJ_;   // gate = first DM cols of proj
    const int tid = threadIdx.x;

    float g[8];
    float ss = 0.f;
#pragma unroll
    for (int k = 0; k < 2; k++) {
        int c = (tid + k * 256) * 4;
        float4 yv = *(const float4*)(yr + c);
        float4 gt = *(const float4*)(gr + c);
        float g0 = yv.x * (gt.x / (1.f + expf(-gt.x)));
        float g1 = yv.y * (gt.y / (1.f + expf(-gt.y)));
        float g2 = yv.z * (gt.z / (1.f + expf(-gt.z)));
        float g3 = yv.w * (gt.w / (1.f + expf(-gt.w)));
        g[k * 4 + 0] = g0; g[k * 4 + 1] = g1;
        g[k * 4 + 2] = g2; g[k * 4 + 3] = g3;
        ss += g0 * g0 + g1 * g1 + g2 * g2 + g3 * g3;
    }
#pragma unroll
    for (int o = 16; o; o >>= 1) ss += __shfl_xor_sync(0xffffffffu, ss, o);
    __shared__ float red[8];
    if ((tid & 31) == 0) red[tid >> 5] = ss;
    __syncthreads();
    float tot = 0.f;
#pragma unroll
    for (int w = 0; w < 8; w++) tot += red[w];
    float scale = rsqrtf(tot * (1.f / (float)DM) + 1e-6f);

#pragma unroll
    for (int k = 0; k < 2; k++) {
        int c = (tid + k * 256) * 4;
        float4 o4;
        o4.x = g[k * 4 + 0] * scale * nw[c + 0];
        o4.y = g[k * 4 + 1] * scale * nw[c + 1];
        o4.z = g[k * 4 + 2] * scale * nw[c + 2];
        o4.w = g[k * 4 + 3] * scale * nw[c + 3];
        *(float4*)(out + (size_t)row * DM + c) = o4;
    }
}

// ---------------------------------------------------------------------------
extern "C" void kernel_launch(void* const* d_in, const int* in_sizes, int n_in,
                              void* d_out, int out_size)
{
    const float* x       = (const float*)d_in[0];
    const float* W_in    = (const float*)d_in[1];
    const float* b_in    = (const float*)d_in[2];
    const float* conv_w  = (const float*)d_in[3];
    const float* conv_b  = (const float*)d_in[4];
    const float* A_log   = (const float*)d_in[5];
    const float* dt_bias = (const float*)d_in[6];
    const float* D_par   = (const float*)d_in[7];
    const float* norm_w  = (const float*)d_in[8];
    const float* W_out   = (const float*)d_in[9];
    float* out = (float*)d_out;

    float *proj, *conv, *dtp, *dAp, *yp, *ynp;
    cudaGetSymbolAddress((void**)&proj, g_proj);
    cudaGetSymbolAddress((void**)&conv, g_conv);
    cudaGetSymbolAddress((void**)&dtp,  g_dt);
    cudaGetSymbolAddress((void**)&dAp,  g_dA);
    cudaGetSymbolAddress((void**)&yp,   g_y);
    cudaGetSymbolAddress((void**)&ynp,  g_yn);

    dim3 blk(256);

    // 1) in_proj GEMM: proj[8192,4192] = x @ W_in + b_in
    gemm128<<<dim3((PROJ_ + 127) / 128, ROWS / 128), blk>>>(
        x, W_in, b_in, proj, ROWS, PROJ_, DM);

    // 2) causal depthwise conv + SiLU on hBC
    conv_silu_kernel<<<(ROWS * CONV_DIM + 255) / 256, blk>>>(
        proj, conv_w, conv_b, conv);

    // 3) dt / dA
    dt_kernel<<<(ROWS * H_ + 255) / 256, blk>>>(proj, dt_bias, A_log, dtp, dAp);

    // 4) selective scan (+ D*x skip)
    scan_kernel<<<B_ * H_, blk>>>(conv, dtp, dAp, D_par, yp);

    // 5) gated RMSNorm
    rmsnorm_kernel<<<ROWS, blk>>>(yp, proj, norm_w, ynp);

    // 6) out_proj GEMM -> d_out
    gemm128<<<dim3(DM / 128, ROWS / 128), blk>>>(
        ynp, W_out, nullptr, out, ROWS, DM, DM);
}